// round 16
// baseline (speedup 1.0000x reference)
#include <cuda_runtime.h>
#include <cuda_fp16.h>
#include <cstdint>

#define DINL __device__ __forceinline__

namespace {
constexpr int   kBatch    = 524288;
constexpr int   kRowsCTA  = 64;                      // 4 warps x 16 rows
constexpr int   kNumTiles = kBatch / kRowsCTA;       // 8192
constexpr int   kThreads  = 128;
constexpr float kDT = 0.01f;

// SMEM offsets in uint32 units
constexpr int OFF_W28   = 0;     // fp8 W2   frags [4 ks][8 np][32 lane] uint4 -> 4096 u32
constexpr int OFF_W2T8  = 4096;  // fp8 W2^T frags, same layout                -> 4096 u32
constexpr int OFF_W1    = 8192;  // f16 W1 k8 frags [8 np][32 lane] uint2      -> 512 u32
constexpr int OFF_W1T   = 8704;  // f16 W1^T frags [8 ks][32 lane] uint2       -> 512 u32
constexpr int OFF_B1    = 9216;  // f32[128]
constexpr int OFF_B2    = 9344;  // f32[128]
constexpr int OFF_W3H   = 9472;  // f16x2[64]  (+16*W3 pairs)
constexpr int OFF_NW3H  = 9536;  // f16x2[64]  (-16*W3 pairs)
constexpr int kSmemU32  = 9600;  // 38400 bytes
// K-permutation baked into fp8 B staging so fp8 A-frags assemble from each
// thread's OWN C pairs (verified bijection: swaps the b2 and tg bit-fields).
__host__ __device__ inline int kmap(int k) {
    int b = k & 3;
    return (k & ~31) | (((k >> 4) & 1) << 4) | ((b >> 1) << 3) | (((k >> 2) & 3) << 1) | (b & 1);
}
}

DINL uint32_t pack_h2(float lo, float hi) {
    __half2 t = __floats2half2_rn(lo, hi);   // .x = lo
    return *reinterpret_cast<uint32_t*>(&t);
}
// f16x2 vector ops
DINL uint32_t tanh2h(uint32_t x) { uint32_t r; asm("tanh.approx.f16x2 %0, %1;" : "=r"(r) : "r"(x)); return r; }
DINL uint32_t mul2h(uint32_t a, uint32_t b) { uint32_t r; asm("mul.rn.f16x2 %0, %1, %2;" : "=r"(r) : "r"(a), "r"(b)); return r; }
DINL uint32_t fma2h(uint32_t a, uint32_t b, uint32_t c) { uint32_t r; asm("fma.rn.f16x2 %0, %1, %2, %3;" : "=r"(r) : "r"(a), "r"(b), "r"(c)); return r; }
DINL uint32_t neg2h(uint32_t a) { uint32_t r; asm("neg.f16x2 %0, %1;" : "=r"(r) : "r"(a)); return r; }
// f16x2 -> e4m3x2 (zero-extended to u32)
DINL uint32_t cvt8(uint32_t h2) {
    uint16_t d; asm("cvt.rn.satfinite.e4m3x2.f16x2 %0, %1;" : "=h"(d) : "r"(h2));
    return (uint32_t)d;
}
// 4 floats -> packed e4m3 bytes [a,b,c,d]
DINL uint32_t e4(float a, float b, float c, float d) {
    uint16_t lo, hi;
    asm("cvt.rn.satfinite.e4m3x2.f32 %0, %1, %2;" : "=h"(lo) : "f"(b), "f"(a));
    asm("cvt.rn.satfinite.e4m3x2.f32 %0, %1, %2;" : "=h"(hi) : "f"(d), "f"(c));
    return (uint32_t)lo | ((uint32_t)hi << 16);
}

// D += A(16x16 f16) x B(16x8 f16), fp32 accum
DINL void mma_h16(float* c, uint32_t a0, uint32_t a1, uint32_t a2, uint32_t a3,
                  uint32_t b0, uint32_t b1) {
    asm volatile(
        "mma.sync.aligned.m16n8k16.row.col.f32.f16.f16.f32 "
        "{%0,%1,%2,%3}, {%4,%5,%6,%7}, {%8,%9}, {%0,%1,%2,%3};"
        : "+f"(c[0]), "+f"(c[1]), "+f"(c[2]), "+f"(c[3])
        : "r"(a0), "r"(a1), "r"(a2), "r"(a3), "r"(b0), "r"(b1));
}
// D += A(16x8 f16) x B(8x8 f16)  (layer 1: true K = 8)
DINL void mma_h8(float* c, uint32_t a0, uint32_t a1, uint32_t b0) {
    asm volatile(
        "mma.sync.aligned.m16n8k8.row.col.f32.f16.f16.f32 "
        "{%0,%1,%2,%3}, {%4,%5}, {%6}, {%0,%1,%2,%3};"
        : "+f"(c[0]), "+f"(c[1]), "+f"(c[2]), "+f"(c[3])
        : "r"(a0), "r"(a1), "r"(b0));
}
// D += A(16x32 e4m3) x B(32x8 e4m3), fp32 accum
DINL void mma_q32(float* c, uint32_t a0, uint32_t a1, uint32_t a2, uint32_t a3,
                  uint32_t b0, uint32_t b1) {
    asm volatile(
        "mma.sync.aligned.m16n8k32.row.col.f32.e4m3.e4m3.f32 "
        "{%0,%1,%2,%3}, {%4,%5,%6,%7}, {%8,%9}, {%0,%1,%2,%3};"
        : "+f"(c[0]), "+f"(c[1]), "+f"(c[2]), "+f"(c[3])
        : "r"(a0), "r"(a1), "r"(a2), "r"(a3), "r"(b0), "r"(b1));
}

// -----------------------------------------------------------------------------
// grad_eval: 16 rows/warp. Layers 2/3 in FP8 (m16n8k32): halves both the mma
// instruction count AND the B-fragment LDS bytes of the dominant GEMMs.
// The kmap-permuted B staging makes fp8 A-frags assemble from each thread's
// own C pairs: hf8[4ks+0] = e4m3x2(tile 4ks, row r) | e4m3x2(tile 4ks+1, row r)<<16, etc.
// Activations scaled x16 before e4m3 (subnormal floor), 1/16 folded into B.
// -----------------------------------------------------------------------------
DINL void grad_eval(const uint4* __restrict__ w2f8, const uint4* __restrict__ w2tf8,
                    const uint2* __restrict__ w1f,  const uint2* __restrict__ w1tf,
                    const float2* __restrict__ b1v, const float2* __restrict__ b2v,
                    const uint32_t* __restrict__ w3h, const uint32_t* __restrict__ nw3h,
                    int lane, const float s[4], float d[4]) {
    const int tg = lane & 3;
    const uint32_t az0 = pack_h2(s[0], s[1]);    // row r,   k=2tg..2tg+1
    const uint32_t az1 = pack_h2(s[2], s[3]);    // row r+8
    const uint32_t k16x2 = 0x4C004C00u;          // f16x2 (16, 16)
    uint32_t hfb[32];   // h1 f16x2 C-pairs; overwritten by dpre1 (layer4 A frags)
    uint32_t hf8[16];   // h1*16 as fp8 A-frags
    uint32_t gf8[16];   // dpre2*16 as fp8 A-frags

    // ---- layer 1 (f16 k8): h1 = tanh(z @ W1 + b1) ----
#pragma unroll
    for (int c = 0; c < 4; c++) {
        float acc[16];
#pragma unroll
        for (int i = 0; i < 16; i++) acc[i] = 0.f;
#pragma unroll
        for (int j = 0; j < 2; j++) {
            const uint2 b = w1f[(2 * c + j) * 32 + lane];
            mma_h8(acc + 8 * j,     az0, az1, b.x);
            mma_h8(acc + 8 * j + 4, az0, az1, b.y);
        }
        uint32_t er[4], er8[4];
#pragma unroll
        for (int j = 0; j < 4; j++) {
            const int nt = 4 * c + j;
            const float2 bb = b1v[nt * 4 + tg];
            uint32_t hr  = tanh2h(pack_h2(acc[4*j]   + bb.x, acc[4*j+1] + bb.y));
            uint32_t hr8 = tanh2h(pack_h2(acc[4*j+2] + bb.x, acc[4*j+3] + bb.y));
            hfb[2*nt]   = hr;
            hfb[2*nt+1] = hr8;
            er[j]  = cvt8(mul2h(hr,  k16x2));
            er8[j] = cvt8(mul2h(hr8, k16x2));
        }
        hf8[4*c+0] = er[0]  | (er[1]  << 16);
        hf8[4*c+1] = er8[0] | (er8[1] << 16);
        hf8[4*c+2] = er[2]  | (er[3]  << 16);
        hf8[4*c+3] = er8[2] | (er8[3] << 16);
    }

    // ---- layer 2 (fp8 k32): dpre2 = w3*(1 - tanh(h1 @ W2 + b2)^2) ----
#pragma unroll
    for (int c = 0; c < 4; c++) {
        float acc[16];
#pragma unroll
        for (int i = 0; i < 16; i++) acc[i] = 0.f;
#pragma unroll
        for (int ks = 0; ks < 4; ks++) {
            const uint4 b0 = w2f8[(ks * 8 + 2 * c)     * 32 + lane];
            const uint4 b1 = w2f8[(ks * 8 + 2 * c + 1) * 32 + lane];
            mma_q32(acc,      hf8[4*ks], hf8[4*ks+1], hf8[4*ks+2], hf8[4*ks+3], b0.x, b0.y);
            mma_q32(acc + 4,  hf8[4*ks], hf8[4*ks+1], hf8[4*ks+2], hf8[4*ks+3], b0.z, b0.w);
            mma_q32(acc + 8,  hf8[4*ks], hf8[4*ks+1], hf8[4*ks+2], hf8[4*ks+3], b1.x, b1.y);
            mma_q32(acc + 12, hf8[4*ks], hf8[4*ks+1], hf8[4*ks+2], hf8[4*ks+3], b1.z, b1.w);
        }
        uint32_t er[4], er8[4];
#pragma unroll
        for (int j = 0; j < 4; j++) {
            const int nt = 4 * c + j;
            const float2 bb = b2v[nt * 4 + tg];
            const uint32_t w3p = w3h[nt * 4 + tg], nw3p = nw3h[nt * 4 + tg];
            uint32_t t  = tanh2h(pack_h2(acc[4*j]   + bb.x, acc[4*j+1] + bb.y));
            uint32_t t8 = tanh2h(pack_h2(acc[4*j+2] + bb.x, acc[4*j+3] + bb.y));
            er[j]  = cvt8(fma2h(nw3p, mul2h(t,  t),  w3p));   // = 16*w3*(1-t^2)
            er8[j] = cvt8(fma2h(nw3p, mul2h(t8, t8), w3p));
        }
        gf8[4*c+0] = er[0]  | (er[1]  << 16);
        gf8[4*c+1] = er8[0] | (er8[1] << 16);
        gf8[4*c+2] = er[2]  | (er[3]  << 16);
        gf8[4*c+3] = er8[2] | (er8[3] << 16);
    }

    // ---- layer 3 (fp8 k32): dpre1 = (dpre2 @ W2^T) * (1 - h1^2) -> hfb in place ----
#pragma unroll
    for (int c = 0; c < 4; c++) {
        float acc[16];
#pragma unroll
        for (int i = 0; i < 16; i++) acc[i] = 0.f;
#pragma unroll
        for (int ks = 0; ks < 4; ks++) {
            const uint4 b0 = w2tf8[(ks * 8 + 2 * c)     * 32 + lane];
            const uint4 b1 = w2tf8[(ks * 8 + 2 * c + 1) * 32 + lane];
            mma_q32(acc,      gf8[4*ks], gf8[4*ks+1], gf8[4*ks+2], gf8[4*ks+3], b0.x, b0.y);
            mma_q32(acc + 4,  gf8[4*ks], gf8[4*ks+1], gf8[4*ks+2], gf8[4*ks+3], b0.z, b0.w);
            mma_q32(acc + 8,  gf8[4*ks], gf8[4*ks+1], gf8[4*ks+2], gf8[4*ks+3], b1.x, b1.y);
            mma_q32(acc + 12, gf8[4*ks], gf8[4*ks+1], gf8[4*ks+2], gf8[4*ks+3], b1.z, b1.w);
        }
#pragma unroll
        for (int j = 0; j < 4; j++) {
            const int nt = 4 * c + j;
            uint32_t v  = pack_h2(acc[4*j],   acc[4*j+1]);
            uint32_t v8 = pack_h2(acc[4*j+2], acc[4*j+3]);
            const uint32_t h = hfb[2*nt], h8 = hfb[2*nt+1];
            hfb[2*nt]   = fma2h(neg2h(v),  mul2h(h,  h),  v);
            hfb[2*nt+1] = fma2h(neg2h(v8), mul2h(h8, h8), v8);
        }
    }

    // ---- layer 4 (f16 k16): dz = dpre1 @ W1^T ----
    d[0] = d[1] = d[2] = d[3] = 0.f;
#pragma unroll
    for (int ks = 0; ks < 8; ks++) {
        const uint2 bw = w1tf[ks * 32 + lane];
        mma_h16(d, hfb[4*ks], hfb[4*ks+1], hfb[4*ks+2], hfb[4*ks+3], bw.x, bw.y);
    }
}

// -----------------------------------------------------------------------------
__global__ void __launch_bounds__(kThreads, 2)
symp_kernel(const float* __restrict__ z,  const float* __restrict__ W1,
            const float* __restrict__ b1, const float* __restrict__ W2,
            const float* __restrict__ b2, const float* __restrict__ W3,
            const float* __restrict__ b3, float* __restrict__ out) {
    extern __shared__ uint32_t sm[];
    const int tid = threadIdx.x;
    const int wid = tid >> 5, lane = tid & 31;
    constexpr float inv16 = 1.0f / 16.0f;

    // ---- stage fp8 W2 / W2^T B-frags with kmap permutation (once per CTA) ----
    // layout: [4 ks][8 np][32 lane] uint4 = {b0(nt0), b1(nt0), b0(nt1), b1(nt1)}
    for (int idx = tid; idx < 4 * 8 * 32; idx += kThreads) {
        int ks = idx >> 8, np = (idx >> 5) & 7, ln = idx & 31;
        int n0 = 16 * np + (ln >> 2);
        int n1 = n0 + 8;
        int kb = 4 * (ln & 3);
        int K0[4], K1[4];
#pragma unroll
        for (int j = 0; j < 4; j++) {
            K0[j] = kmap(32 * ks + kb + j);        // b0 rows
            K1[j] = kmap(32 * ks + 16 + kb + j);   // b1 rows
        }
        ((uint4*)(sm + OFF_W28))[idx] = make_uint4(
            e4(W2[K0[0]*128+n0]*inv16, W2[K0[1]*128+n0]*inv16, W2[K0[2]*128+n0]*inv16, W2[K0[3]*128+n0]*inv16),
            e4(W2[K1[0]*128+n0]*inv16, W2[K1[1]*128+n0]*inv16, W2[K1[2]*128+n0]*inv16, W2[K1[3]*128+n0]*inv16),
            e4(W2[K0[0]*128+n1]*inv16, W2[K0[1]*128+n1]*inv16, W2[K0[2]*128+n1]*inv16, W2[K0[3]*128+n1]*inv16),
            e4(W2[K1[0]*128+n1]*inv16, W2[K1[1]*128+n1]*inv16, W2[K1[2]*128+n1]*inv16, W2[K1[3]*128+n1]*inv16));
        ((uint4*)(sm + OFF_W2T8))[idx] = make_uint4(
            e4(W2[n0*128+K0[0]]*inv16, W2[n0*128+K0[1]]*inv16, W2[n0*128+K0[2]]*inv16, W2[n0*128+K0[3]]*inv16),
            e4(W2[n0*128+K1[0]]*inv16, W2[n0*128+K1[1]]*inv16, W2[n0*128+K1[2]]*inv16, W2[n0*128+K1[3]]*inv16),
            e4(W2[n1*128+K0[0]]*inv16, W2[n1*128+K0[1]]*inv16, W2[n1*128+K0[2]]*inv16, W2[n1*128+K0[3]]*inv16),
            e4(W2[n1*128+K1[0]]*inv16, W2[n1*128+K1[1]]*inv16, W2[n1*128+K1[2]]*inv16, W2[n1*128+K1[3]]*inv16));
    }
    for (int idx = tid; idx < 8 * 32; idx += kThreads) {    // W1 f16 k8 frag pairs
        int np = idx >> 5, ln = idx & 31;
        int n0 = 16 * np + (ln >> 2);
        int n1 = n0 + 8;
        int kb = (ln & 3) * 2;
        ((uint2*)(sm + OFF_W1))[idx] = make_uint2(
            pack_h2(W1[kb * 128 + n0], W1[(kb + 1) * 128 + n0]),
            pack_h2(W1[kb * 128 + n1], W1[(kb + 1) * 128 + n1]));
    }
    for (int idx = tid; idx < 8 * 32; idx += kThreads) {    // W1^T f16: B(k,n)=W1[n*128+k]
        int ks = idx >> 5, ln = idx & 31;
        int n  = ln >> 2;
        int kb = ks * 16 + (ln & 3) * 2;
        ((uint2*)(sm + OFF_W1T))[idx] = make_uint2(
            pack_h2(W1[n * 128 + kb],     W1[n * 128 + kb + 1]),
            pack_h2(W1[n * 128 + kb + 8], W1[n * 128 + kb + 9]));
    }
    ((float*)(sm + OFF_B1))[tid] = b1[tid];
    ((float*)(sm + OFF_B2))[tid] = b2[tid];
    if (tid < 64) {
        sm[OFF_W3H  + tid] = pack_h2( 16.f * W3[2 * tid],  16.f * W3[2 * tid + 1]);
        sm[OFF_NW3H + tid] = pack_h2(-16.f * W3[2 * tid], -16.f * W3[2 * tid + 1]);
    }
    __syncthreads();

    const uint4*    w2f8  = (const uint4*)(sm + OFF_W28);
    const uint4*    w2tf8 = (const uint4*)(sm + OFF_W2T8);
    const uint2*    w1f   = (const uint2*)(sm + OFF_W1);
    const uint2*    w1tf  = (const uint2*)(sm + OFF_W1T);
    const float2*   b1v   = (const float2*)(sm + OFF_B1);
    const float2*   b2v   = (const float2*)(sm + OFF_B2);
    const uint32_t* w3h   = (const uint32_t*)(sm + OFF_W3H);
    const uint32_t* nw3h  = (const uint32_t*)(sm + OFF_NW3H);
    (void)b3;  // constant offset: no effect on gradient

    const int gp = lane >> 2, tg = lane & 3;

    for (int t = blockIdx.x; t < kNumTiles; t += gridDim.x) {
        const int row0 = t * kRowsCTA + wid * 16;
        const float* zp = z + (size_t)(row0 + gp) * 8 + tg * 2;
        float s[4];
        {
            float2 v0 = *(const float2*)zp;          // row g
            float2 v1 = *(const float2*)(zp + 64);   // row g+8
            s[0] = v0.x; s[1] = v0.y; s[2] = v1.x; s[3] = v1.y;
        }
        float d[4], dsw[4];
#pragma unroll 1
        for (int it = 0; it < 4; it++) {
            grad_eval(w2f8, w2tf8, w1f, w1tf, b1v, b2v, w3h, nw3h, lane, s, d);
#pragma unroll
            for (int i = 0; i < 4; i++) dsw[i] = __shfl_xor_sync(0xffffffffu, d[i], 2);
            if ((it & 1) == 0) {
                if (tg < 2) {               // q cols: q += dt * dHdp
#pragma unroll
                    for (int i = 0; i < 4; i++) s[i] += kDT * dsw[i];
                } else {                    // p cols: p -= dt/2 * dHdq
#pragma unroll
                    for (int i = 0; i < 4; i++) s[i] -= 0.5f * kDT * dsw[i];
                }
            } else {
                if (tg >= 2) {              // p cols: p = p_half - dt/2 * dHdq_new
#pragma unroll
                    for (int i = 0; i < 4; i++) s[i] -= 0.5f * kDT * dsw[i];
                }
            }
        }
        float* op = out + (size_t)(row0 + gp) * 8 + tg * 2;
        *(float2*)op        = make_float2(s[0], s[1]);
        *(float2*)(op + 64) = make_float2(s[2], s[3]);
    }
}

extern "C" void kernel_launch(void* const* d_in, const int* in_sizes, int n_in,
                              void* d_out, int out_size) {
    const float* z  = (const float*)d_in[0];
    const float* W1 = (const float*)d_in[1];
    const float* b1 = (const float*)d_in[2];
    const float* W2 = (const float*)d_in[3];
    const float* b2 = (const float*)d_in[4];
    const float* W3 = (const float*)d_in[5];
    const float* b3 = (const float*)d_in[6];
    constexpr int kSmemBytes = kSmemU32 * 4;
    cudaFuncSetAttribute(symp_kernel, cudaFuncAttributeMaxDynamicSharedMemorySize, kSmemBytes);
    int grid = 296;                       // 2 persistent CTAs / SM x 148 SMs
    if (grid > kNumTiles) grid = kNumTiles;
    symp_kernel<<<grid, kThreads, kSmemBytes>>>(z, W1, b1, W2, b2, W3, b3, (float*)d_out);
    (void)in_sizes; (void)n_in; (void)out_size;
}

// round 17
// speedup vs baseline: 1.0129x; 1.0129x over previous
#include <cuda_runtime.h>
#include <cuda_bf16.h>
#include <cstdint>

#define DINL __device__ __forceinline__

namespace {
constexpr int   kBatch    = 524288;
constexpr int   kRowsTile = 16;                      // one 16-row tile per warp-iter
constexpr int   kNumTiles = kBatch / kRowsTile;      // 32768
constexpr int   kThreads  = 160;                     // 5 warps/CTA -> 10 warps/SM @ 2 CTAs
constexpr int   kGrid     = 296;                     // 2 CTAs x 148 SMs
constexpr float kDT = 0.01f;

// SMEM offsets in uint32 units
constexpr int OFF_W2   = 0;      // W2  B-frags [8 ks][8 np][32 lane] uint4 -> 8192 u32
constexpr int OFF_W2T  = 8192;   // W2^T B-frags, same layout               -> 8192 u32
constexpr int OFF_W1   = 16384;  // W1 k8 B-frags [8 np][32 lane] uint2     -> 512 u32
constexpr int OFF_W1T  = 16896;  // W1^T B-frags [8 ks][32 lane] uint2      -> 512 u32
constexpr int OFF_B1   = 17408;  // f32[128]
constexpr int OFF_B2   = 17536;  // f32[128]
constexpr int OFF_W3B  = 17664;  // bf16x2[64]  (+W3 pairs)
constexpr int OFF_NW3B = 17728;  // bf16x2[64]  (-W3 pairs)
constexpr int kSmemU32 = 17792;  // 71168 bytes -> 2 CTAs/SM
}

DINL uint32_t pack_bf2(float lo, float hi) {
    __nv_bfloat162 t = __floats2bfloat162_rn(lo, hi);
    return *reinterpret_cast<uint32_t*>(&t);
}
// bf16x2 vector ops (HFMA2/MUFU pipes)
DINL uint32_t tanh2(uint32_t x) { uint32_t r; asm("tanh.approx.bf16x2 %0, %1;" : "=r"(r) : "r"(x)); return r; }
DINL uint32_t mul2(uint32_t a, uint32_t b) { uint32_t r; asm("mul.rn.bf16x2 %0, %1, %2;" : "=r"(r) : "r"(a), "r"(b)); return r; }
DINL uint32_t fma2(uint32_t a, uint32_t b, uint32_t c) { uint32_t r; asm("fma.rn.bf16x2 %0, %1, %2, %3;" : "=r"(r) : "r"(a), "r"(b), "r"(c)); return r; }
DINL uint32_t neg2(uint32_t a) { uint32_t r; asm("neg.bf16x2 %0, %1;" : "=r"(r) : "r"(a)); return r; }

// D = A(16x16 bf16) x B(16x8 bf16) + D, fp32 accum
DINL void mma16816(float* c, uint32_t a0, uint32_t a1, uint32_t a2, uint32_t a3,
                   uint32_t b0, uint32_t b1) {
    asm volatile(
        "mma.sync.aligned.m16n8k16.row.col.f32.bf16.bf16.f32 "
        "{%0,%1,%2,%3}, {%4,%5,%6,%7}, {%8,%9}, {%0,%1,%2,%3};"
        : "+f"(c[0]), "+f"(c[1]), "+f"(c[2]), "+f"(c[3])
        : "r"(a0), "r"(a1), "r"(a2), "r"(a3), "r"(b0), "r"(b1));
}
// D = A(16x8 bf16) x B(8x8 bf16) + D (layer 1: true K = 8)
DINL void mma16808(float* c, uint32_t a0, uint32_t a1, uint32_t b0) {
    asm volatile(
        "mma.sync.aligned.m16n8k8.row.col.f32.bf16.bf16.f32 "
        "{%0,%1,%2,%3}, {%4,%5}, {%6}, {%0,%1,%2,%3};"
        : "+f"(c[0]), "+f"(c[1]), "+f"(c[2]), "+f"(c[3])
        : "r"(a0), "r"(a1), "r"(b0));
}

// -----------------------------------------------------------------------------
// grad_eval: 16 rows/warp, layers 1-3 chunked by 4 nt (acc[16] live), all ks
// loops fully unrolled (compile-time fragment indices), bf16x2 elementwise,
// layer-3 output overwrites hf in place. This low-pressure structure fit a
// 168-reg cap with only mild spills (R15), so the 204-reg cap of
// __launch_bounds__(160,2) fits with zero spills -> 10 warps/SM.
// -----------------------------------------------------------------------------
DINL void grad_eval(const uint4* __restrict__ w2f,  const uint4* __restrict__ w2tf,
                    const uint2* __restrict__ w1f,  const uint2* __restrict__ w1tf,
                    const float2* __restrict__ b1v, const float2* __restrict__ b2v,
                    const uint32_t* __restrict__ w3b, const uint32_t* __restrict__ nw3b,
                    int lane, const float s[4], float d[4]) {
    const int tg = lane & 3;
    const uint32_t az0 = pack_bf2(s[0], s[1]);   // row g,   k=2tg..2tg+1
    const uint32_t az1 = pack_bf2(s[2], s[3]);   // row g+8
    uint32_t hf[32];   // h1 A-frags (K=128); overwritten by dpre1 in layer 3
    uint32_t gf[32];   // dpre2 A-frags

    // ---- layer 1 (k8): h1 = tanh(z @ W1 + b1), chunks of 4 nt ----
#pragma unroll
    for (int c = 0; c < 4; c++) {
        float acc[16];
#pragma unroll
        for (int i = 0; i < 16; i++) acc[i] = 0.f;
#pragma unroll
        for (int j = 0; j < 2; j++) {
            const uint2 b = w1f[(2 * c + j) * 32 + lane];
            mma16808(acc + 8 * j,     az0, az1, b.x);
            mma16808(acc + 8 * j + 4, az0, az1, b.y);
        }
#pragma unroll
        for (int j = 0; j < 4; j++) {
            const int nt = 4 * c + j;
            const float2 bb = b1v[nt * 4 + tg];
            hf[2*nt]   = tanh2(pack_bf2(acc[4*j]   + bb.x, acc[4*j+1] + bb.y));
            hf[2*nt+1] = tanh2(pack_bf2(acc[4*j+2] + bb.x, acc[4*j+3] + bb.y));
        }
    }

    // ---- layer 2: dpre2 = w3*(1 - tanh(h1 @ W2 + b2)^2), chunks of 4 nt ----
#pragma unroll
    for (int c = 0; c < 4; c++) {
        float acc[16];
#pragma unroll
        for (int i = 0; i < 16; i++) acc[i] = 0.f;
#pragma unroll
        for (int ks = 0; ks < 8; ks++) {
            const uint4 b0 = w2f[(ks * 8 + 2 * c)     * 32 + lane];
            const uint4 b1 = w2f[(ks * 8 + 2 * c + 1) * 32 + lane];
            mma16816(acc,      hf[4*ks], hf[4*ks+1], hf[4*ks+2], hf[4*ks+3], b0.x, b0.y);
            mma16816(acc + 4,  hf[4*ks], hf[4*ks+1], hf[4*ks+2], hf[4*ks+3], b0.z, b0.w);
            mma16816(acc + 8,  hf[4*ks], hf[4*ks+1], hf[4*ks+2], hf[4*ks+3], b1.x, b1.y);
            mma16816(acc + 12, hf[4*ks], hf[4*ks+1], hf[4*ks+2], hf[4*ks+3], b1.z, b1.w);
        }
#pragma unroll
        for (int j = 0; j < 4; j++) {
            const int nt = 4 * c + j;
            const float2 bb = b2v[nt * 4 + tg];
            const uint32_t w3p  = w3b[nt * 4 + tg];
            const uint32_t nw3p = nw3b[nt * 4 + tg];
            uint32_t t0 = tanh2(pack_bf2(acc[4*j]   + bb.x, acc[4*j+1] + bb.y));
            uint32_t t1 = tanh2(pack_bf2(acc[4*j+2] + bb.x, acc[4*j+3] + bb.y));
            gf[2*nt]   = fma2(nw3p, mul2(t0, t0), w3p);
            gf[2*nt+1] = fma2(nw3p, mul2(t1, t1), w3p);
        }
    }

    // ---- layer 3: dpre1 = (dpre2 @ W2^T) * (1 - h1^2), writes hf in place ----
#pragma unroll
    for (int c = 0; c < 4; c++) {
        float acc[16];
#pragma unroll
        for (int i = 0; i < 16; i++) acc[i] = 0.f;
#pragma unroll
        for (int ks = 0; ks < 8; ks++) {
            const uint4 b0 = w2tf[(ks * 8 + 2 * c)     * 32 + lane];
            const uint4 b1 = w2tf[(ks * 8 + 2 * c + 1) * 32 + lane];
            mma16816(acc,      gf[4*ks], gf[4*ks+1], gf[4*ks+2], gf[4*ks+3], b0.x, b0.y);
            mma16816(acc + 4,  gf[4*ks], gf[4*ks+1], gf[4*ks+2], gf[4*ks+3], b0.z, b0.w);
            mma16816(acc + 8,  gf[4*ks], gf[4*ks+1], gf[4*ks+2], gf[4*ks+3], b1.x, b1.y);
            mma16816(acc + 12, gf[4*ks], gf[4*ks+1], gf[4*ks+2], gf[4*ks+3], b1.z, b1.w);
        }
#pragma unroll
        for (int j = 0; j < 4; j++) {
            const int nt = 4 * c + j;
            uint32_t v0 = pack_bf2(acc[4*j],   acc[4*j+1]);
            uint32_t v1 = pack_bf2(acc[4*j+2], acc[4*j+3]);
            const uint32_t h0 = hf[2*nt], h1 = hf[2*nt+1];
            hf[2*nt]   = fma2(neg2(v0), mul2(h0, h0), v0);
            hf[2*nt+1] = fma2(neg2(v1), mul2(h1, h1), v1);
        }
    }

    // ---- layer 4: dz = dpre1 @ W1^T ----
    d[0] = d[1] = d[2] = d[3] = 0.f;
#pragma unroll
    for (int ks = 0; ks < 8; ks++) {
        const uint2 bw = w1tf[ks * 32 + lane];
        mma16816(d, hf[4*ks], hf[4*ks+1], hf[4*ks+2], hf[4*ks+3], bw.x, bw.y);
    }
}

// -----------------------------------------------------------------------------
__global__ void __launch_bounds__(kThreads, 2)
symp_kernel(const float* __restrict__ z,  const float* __restrict__ W1,
            const float* __restrict__ b1, const float* __restrict__ W2,
            const float* __restrict__ b2, const float* __restrict__ W3,
            const float* __restrict__ b3, float* __restrict__ out) {
    extern __shared__ uint32_t sm[];
    const int tid = threadIdx.x;
    const int wid = tid >> 5, lane = tid & 31;

    // ---- build weight B-fragments in SMEM (once per persistent CTA) ----
    for (int idx = tid; idx < 8 * 8 * 32; idx += kThreads) {
        int ks = idx >> 8, np = (idx >> 5) & 7, ln = idx & 31;
        int n0 = (2 * np) * 8 + (ln >> 2);
        int n1 = n0 + 8;
        int kb = ks * 16 + (ln & 3) * 2;
        ((uint4*)(sm + OFF_W2))[idx] = make_uint4(
            pack_bf2(W2[kb * 128 + n0],       W2[(kb + 1) * 128 + n0]),
            pack_bf2(W2[(kb + 8) * 128 + n0], W2[(kb + 9) * 128 + n0]),
            pack_bf2(W2[kb * 128 + n1],       W2[(kb + 1) * 128 + n1]),
            pack_bf2(W2[(kb + 8) * 128 + n1], W2[(kb + 9) * 128 + n1]));
        ((uint4*)(sm + OFF_W2T))[idx] = make_uint4(
            pack_bf2(W2[n0 * 128 + kb],     W2[n0 * 128 + kb + 1]),
            pack_bf2(W2[n0 * 128 + kb + 8], W2[n0 * 128 + kb + 9]),
            pack_bf2(W2[n1 * 128 + kb],     W2[n1 * 128 + kb + 1]),
            pack_bf2(W2[n1 * 128 + kb + 8], W2[n1 * 128 + kb + 9]));
    }
    for (int idx = tid; idx < 8 * 32; idx += kThreads) {    // W1 k8 frag pairs
        int np = idx >> 5, ln = idx & 31;
        int n0 = (2 * np) * 8 + (ln >> 2);
        int n1 = n0 + 8;
        int kb = (ln & 3) * 2;
        ((uint2*)(sm + OFF_W1))[idx] = make_uint2(
            pack_bf2(W1[kb * 128 + n0], W1[(kb + 1) * 128 + n0]),
            pack_bf2(W1[kb * 128 + n1], W1[(kb + 1) * 128 + n1]));
    }
    for (int idx = tid; idx < 8 * 32; idx += kThreads) {    // W1^T: B(k,n) = W1[n*128+k]
        int ks = idx >> 5, ln = idx & 31;
        int n  = ln >> 2;
        int kb = ks * 16 + (ln & 3) * 2;
        ((uint2*)(sm + OFF_W1T))[idx] = make_uint2(
            pack_bf2(W1[n * 128 + kb],     W1[n * 128 + kb + 1]),
            pack_bf2(W1[n * 128 + kb + 8], W1[n * 128 + kb + 9]));
    }
    if (tid < 128) {
        ((float*)(sm + OFF_B1))[tid] = b1[tid];
        ((float*)(sm + OFF_B2))[tid] = b2[tid];
    }
    if (tid < 64) {
        sm[OFF_W3B  + tid] = pack_bf2( W3[2 * tid],  W3[2 * tid + 1]);
        sm[OFF_NW3B + tid] = pack_bf2(-W3[2 * tid], -W3[2 * tid + 1]);
    }
    __syncthreads();

    const uint4*    w2f  = (const uint4*)(sm + OFF_W2);
    const uint4*    w2tf = (const uint4*)(sm + OFF_W2T);
    const uint2*    w1f  = (const uint2*)(sm + OFF_W1);
    const uint2*    w1tf = (const uint2*)(sm + OFF_W1T);
    const float2*   b1v  = (const float2*)(sm + OFF_B1);
    const float2*   b2v  = (const float2*)(sm + OFF_B2);
    const uint32_t* w3b  = (const uint32_t*)(sm + OFF_W3B);
    const uint32_t* nw3b = (const uint32_t*)(sm + OFF_NW3B);
    (void)b3;  // constant offset: no effect on gradient

    const int gp = lane >> 2, tg = lane & 3;
    const int gwarp  = blockIdx.x * (kThreads / 32) + wid;   // global warp id
    const int nwarps = kGrid * (kThreads / 32);              // 1480

    for (int t = gwarp; t < kNumTiles; t += nwarps) {
        const int row0 = t * kRowsTile;
        const float* zp = z + (size_t)(row0 + gp) * 8 + tg * 2;
        float s[4];
        {
            float2 v0 = *(const float2*)zp;          // row g
            float2 v1 = *(const float2*)(zp + 64);   // row g+8
            s[0] = v0.x; s[1] = v0.y; s[2] = v1.x; s[3] = v1.y;
        }
        float d[4], dsw[4];
#pragma unroll 1
        for (int it = 0; it < 4; it++) {
            grad_eval(w2f, w2tf, w1f, w1tf, b1v, b2v, w3b, nw3b, lane, s, d);
#pragma unroll
            for (int i = 0; i < 4; i++) dsw[i] = __shfl_xor_sync(0xffffffffu, d[i], 2);
            if ((it & 1) == 0) {
                if (tg < 2) {               // q cols: q += dt * dHdp
#pragma unroll
                    for (int i = 0; i < 4; i++) s[i] += kDT * dsw[i];
                } else {                    // p cols: p -= dt/2 * dHdq
#pragma unroll
                    for (int i = 0; i < 4; i++) s[i] -= 0.5f * kDT * dsw[i];
                }
            } else {
                if (tg >= 2) {              // p cols: p = p_half - dt/2 * dHdq_new
#pragma unroll
                    for (int i = 0; i < 4; i++) s[i] -= 0.5f * kDT * dsw[i];
                }
            }
        }
        float* op = out + (size_t)(row0 + gp) * 8 + tg * 2;
        *(float2*)op        = make_float2(s[0], s[1]);
        *(float2*)(op + 64) = make_float2(s[2], s[3]);
    }
}

extern "C" void kernel_launch(void* const* d_in, const int* in_sizes, int n_in,
                              void* d_out, int out_size) {
    const float* z  = (const float*)d_in[0];
    const float* W1 = (const float*)d_in[1];
    const float* b1 = (const float*)d_in[2];
    const float* W2 = (const float*)d_in[3];
    const float* b2 = (const float*)d_in[4];
    const float* W3 = (const float*)d_in[5];
    const float* b3 = (const float*)d_in[6];
    constexpr int kSmemBytes = kSmemU32 * 4;
    cudaFuncSetAttribute(symp_kernel, cudaFuncAttributeMaxDynamicSharedMemorySize, kSmemBytes);
    symp_kernel<<<kGrid, kThreads, kSmemBytes>>>(z, W1, b1, W2, b2, W3, b3, (float*)d_out);
    (void)in_sizes; (void)n_in; (void)out_size;
}